// round 7
// baseline (speedup 1.0000x reference)
#include <cuda_runtime.h>

#define NUM_SKILLS 300
#define EMB 256
#define CD 64
#define BB 512
#define SS 200
#define RPB 40            // rows per block in main kernel
#define SEGS (SS / RPB)   // 5 segments per batch row
#define RPW (RPB / 8)     // 5 rows per warp in count phase

// Coefficient scratch. out[b,s,e] = qf*A[e] + att*B[e] + mast*C[e] + D[e]
__device__ float g_A[EMB], g_B[EMB], g_C[EMB], g_D[EMB];

// ---------------------------------------------------------------------------
// K1: coefficient kernel. 32 blocks x 256 threads = 256 warps, ONE warp per e.
// ---------------------------------------------------------------------------
__global__ void __launch_bounds__(256) coef_kernel(
    const float* __restrict__ skill_w, const float* __restrict__ skill_b,
    const float* __restrict__ att_w,   const float* __restrict__ att_b,
    const float* __restrict__ mast_w,  const float* __restrict__ mast_b,
    const float* __restrict__ proj_w,  const float* __restrict__ proj_b)
{
    const int e    = blockIdx.x * 8 + (threadIdx.x >> 5);   // 0..255
    const int lane = threadIdx.x & 31;
    const int chi  = lane + 32;

    const float wlo = (lane < 21) ? skill_w[lane] : att_w[lane - 21];
    const float blo = (lane < 21) ? skill_b[lane] : att_b[lane - 21];
    const float whi = (chi  < 42) ? att_w[chi - 21] : mast_w[chi - 42];
    const float bhi = (chi  < 42) ? att_b[chi - 21] : mast_b[chi - 42];

    const float p0 = proj_w[e * CD + lane];   // coalesced
    const float p1 = proj_w[e * CD + chi];    // coalesced

    const bool loA = lane < 21;
    const bool hiB = chi  < 42;

    float av = loA ? p0 * wlo : 0.0f;
    float bv = (loA ? 0.0f : p0 * wlo) + (hiB ? p1 * whi : 0.0f);
    float cv = hiB ? 0.0f : p1 * whi;
    float dv = fmaf(p0, blo, p1 * bhi);

    #pragma unroll
    for (int off = 16; off > 0; off >>= 1) {
        av += __shfl_xor_sync(0xFFFFFFFF, av, off);
        bv += __shfl_xor_sync(0xFFFFFFFF, bv, off);
        cv += __shfl_xor_sync(0xFFFFFFFF, cv, off);
        dv += __shfl_xor_sync(0xFFFFFFFF, dv, off);
    }
    if (lane == 0) {
        g_A[e] = av; g_B[e] = bv; g_C[e] = cv;
        g_D[e] = dv + proj_b[e];
    }
}

// ---------------------------------------------------------------------------
// K2: main kernel. 2560 blocks x 256 threads. Block = (batch b, 40-row seg).
// Phase 1: coalesced prefix load -> shared pack[]; coeff float4s -> registers.
// Phase 2: WARP-PARALLEL counts. Warp w owns rows w, w+8, ..., w+32 (5 rows).
//          For each row s: lanes sweep the prefix 32 elements at a time,
//          match via compare, reduce via __ballot_sync + __popc. ~7 chunks
//          per row -> ~35 iterations per warp, all 8 warps busy.
// Phase 3: store. Thread owns e4 = t&63, rows lane+4i (lane = t>>6, i<10):
//          1 broadcast LDS + 12 FMA + 1 STG.128.CS per 16B of output.
// ---------------------------------------------------------------------------
__global__ void __launch_bounds__(256) main_kernel(
    const int* __restrict__ q, const int* __restrict__ r,
    float* __restrict__ out)
{
    __shared__ int    pack[SS];     // qc | valid<<9 | r<<10
    __shared__ float4 scal[RPB];    // {qf, att, mast, valid}

    const int t   = threadIdx.x;
    const int b   = blockIdx.x / SEGS;
    const int s0  = (blockIdx.x % SEGS) * RPB;
    const int n   = s0 + RPB;       // prefix length needed

    // Phase 1a: prefix input loads first (they gate both barriers).
    int qraw = 0, rraw = 0;
    if (t < n) {
        qraw = q[b * SS + t];
        rraw = r[b * SS + t];
    }

    // Phase 1b: coefficient fetch (independent; overlaps the loads above).
    const int e4 = t & 63;
    const float4 a  = __ldg(&reinterpret_cast<const float4*>(g_A)[e4]);
    const float4 bc = __ldg(&reinterpret_cast<const float4*>(g_B)[e4]);
    const float4 cc = __ldg(&reinterpret_cast<const float4*>(g_C)[e4]);
    const float4 dc = __ldg(&reinterpret_cast<const float4*>(g_D)[e4]);

    if (t < n) {
        const int v  = (qraw >= 0) & (qraw < NUM_SKILLS);
        int qc = qraw < 0 ? 0 : (qraw > NUM_SKILLS - 1 ? NUM_SKILLS - 1 : qraw);
        pack[t] = qc | (v << 9) | ((rraw & 1) << 10);
    }
    __syncthreads();

    // Phase 2: warp-parallel counts via ballot/popc.
    {
        const int w    = t >> 5;      // warp 0..7
        const int lane = t & 31;
        #pragma unroll
        for (int rr = 0; rr < RPW; ++rr) {
            const int row = w + rr * 8;          // 0..39, uniform in warp
            const int s   = s0 + row;
            const int w0  = pack[s];             // broadcast
            const int myq = w0 & 0x1FF;
            int att = 0, cor = 0;
            const int nchunk = (s + 32) >> 5;    // ceil((s+1)/32)
            for (int k = 0; k < nchunk; ++k) {
                const int tp  = (k << 5) + lane;
                const int idx = tp <= s ? tp : s;      // stay in-bounds
                const int pw  = pack[idx];             // conflict-free LDS
                const bool in = tp <= s;
                const bool m  = in && (((pw & 0x1FF) == myq) & ((pw >> 9) & 1));
                const unsigned bm = __ballot_sync(0xFFFFFFFF, m);
                const unsigned bcr = __ballot_sync(0xFFFFFFFF, m && ((pw >> 10) & 1));
                att += __popc(bm);
                cor += __popc(bcr);
            }
            if (lane == 0) {
                const float attf = (float)att;
                const float mast = (float)cor / fmaxf(attf, 1.0f);
                const float vf   = ((w0 >> 9) & 1) ? 1.0f : 0.0f;
                scal[row] = make_float4((float)myq, attf, mast, vf);
            }
        }
    }
    __syncthreads();

    // Phase 3: store loop.
    const int lane4 = t >> 6;                        // 0..3
    float4* __restrict__ out4 = reinterpret_cast<float4*>(out);
    const int base = (b * SS + s0) * (EMB / 4) + e4; // float4 index of row s0

    #pragma unroll
    for (int i = 0; i < RPB / 4; ++i) {
        const int row = lane4 + i * 4;               // 0..39, uniform per warp
        const float4 s = scal[row];                  // LDS broadcast
        float4 o;
        if (s.w != 0.0f) {
            o.x = fmaf(s.x, a.x, fmaf(s.y, bc.x, fmaf(s.z, cc.x, dc.x)));
            o.y = fmaf(s.x, a.y, fmaf(s.y, bc.y, fmaf(s.z, cc.y, dc.y)));
            o.z = fmaf(s.x, a.z, fmaf(s.y, bc.z, fmaf(s.z, cc.z, dc.z)));
            o.w = fmaf(s.x, a.w, fmaf(s.y, bc.w, fmaf(s.z, cc.w, dc.w)));
        } else {
            o = make_float4(0.f, 0.f, 0.f, 0.f);
        }
        __stcs(&out4[base + row * (EMB / 4)], o);    // streaming store
    }
}

// Input order (metadata): 0=q 1=r 2=qry(unused) 3=skill_w 4=skill_b
// 5=att_w 6=att_b 7=mast_w 8=mast_b 9=proj_w 10=proj_b
extern "C" void kernel_launch(void* const* d_in, const int* in_sizes, int n_in,
                              void* d_out, int out_size)
{
    const int*   q       = (const int*)d_in[0];
    const int*   r       = (const int*)d_in[1];
    const float* skill_w = (const float*)d_in[3];
    const float* skill_b = (const float*)d_in[4];
    const float* att_w   = (const float*)d_in[5];
    const float* att_b   = (const float*)d_in[6];
    const float* mast_w  = (const float*)d_in[7];
    const float* mast_b  = (const float*)d_in[8];
    const float* proj_w  = (const float*)d_in[9];
    const float* proj_b  = (const float*)d_in[10];
    float* out = (float*)d_out;

    coef_kernel<<<EMB / 8, 256>>>(skill_w, skill_b, att_w, att_b,
                                  mast_w, mast_b, proj_w, proj_b);

    main_kernel<<<BB * SEGS, 256>>>(q, r, out);   // 2560 blocks
}